// round 5
// baseline (speedup 1.0000x reference)
#include <cuda_runtime.h>

#define B_   16
#define T_   48
#define N_   500
#define D_   64
#define SP   68          // padded row stride (floats) for Q/K/V/O/T tiles
#define SP4  17          // SP/4
#define SPB  272         // SP bytes
#define SMEM_FLOATS (T_*128 + 3*T_*SP)
#define SMEM_BYTES  (SMEM_FLOATS*4)

typedef unsigned long long u64;

// Packed weights: [mat][kpair][j] (j fast => coalesced LDG.64)
__device__ u64 gWqkv[3 * 64 * 64];   // W12,W13,W14: 64 kpairs x 64 cols
__device__ u64 gW56 [2 * 32 * 64];   // W15,W16:     32 kpairs x 64 cols

__device__ __forceinline__ u64 pack2(float lo, float hi) {
    u64 r; asm("mov.b64 %0, {%1, %2};" : "=l"(r) : "f"(lo), "f"(hi)); return r;
}
__device__ __forceinline__ float2 unpack2(u64 v) {
    float2 f; asm("mov.b64 {%0, %1}, %2;" : "=f"(f.x), "=f"(f.y) : "l"(v)); return f;
}
__device__ __forceinline__ void fma2(u64& d, u64 a, u64 b) {
    asm("fma.rn.f32x2 %0, %1, %2, %0;" : "+l"(d) : "l"(a), "l"(b));
}
__device__ __forceinline__ u64 mul2(u64 a, u64 b) {
    u64 d; asm("mul.rn.f32x2 %0, %1, %2;" : "=l"(d) : "l"(a), "l"(b)); return d;
}
__device__ __forceinline__ void lds2x64(u64& a, u64& b, unsigned addr) {
    asm volatile("ld.shared.v2.b64 {%0,%1}, [%2];" : "=l"(a), "=l"(b) : "r"(addr));
}
__device__ __forceinline__ void sts2x64(unsigned addr, u64 a, u64 b) {
    asm volatile("st.shared.v2.b64 [%0], {%1,%2};" :: "r"(addr), "l"(a), "l"(b));
}

// ---- prep: pack+transpose weights into [kpair][j] u64 layout ----
__global__ void pack_weights(const float* __restrict__ W12, const float* __restrict__ W13,
                             const float* __restrict__ W14, const float* __restrict__ W15,
                             const float* __restrict__ W16)
{
    int idx = blockIdx.x * 256 + threadIdx.x;       // 16384 total
    if (idx < 3 * 4096) {
        int m = idx >> 12, r = idx & 4095;
        int kp = r >> 6, j = r & 63;
        const float* W = (m == 0) ? W12 : (m == 1) ? W13 : W14;
        gWqkv[idx] = pack2(W[(2*kp)*64 + j], W[(2*kp+1)*64 + j]);
    } else if (idx < 3 * 4096 + 2 * 2048) {
        int r = idx - 3 * 4096;
        int m = r >> 11; r &= 2047;
        int kp = r >> 6, j = r & 63;
        const float* W = (m == 0) ? W15 : W16;
        gW56[m*2048 + kp*64 + j] = pack2(W[(2*kp)*64 + j], W[(2*kp+1)*64 + j]);
    }
}

__global__ __launch_bounds__(384, 2)
void fused_temporal_attn(const float* __restrict__ X,  const float* __restrict__ STE,
                         const float* __restrict__ b12, const float* __restrict__ b13,
                         const float* __restrict__ b14, const float* __restrict__ b15,
                         const float* __restrict__ b16,
                         float* __restrict__ out)
{
    extern __shared__ float smem[];
    float* sH = smem;             // [48][128]
    float* sQ = sH + T_*128;      // [48][SP]
    float* sK = sQ + T_*SP;
    float* sV = sK + T_*SP;
    float* sO = sH;               // alias
    float* sT = sQ;               // alias

    const unsigned sHb = (unsigned)__cvta_generic_to_shared(sH);
    const unsigned sQb = (unsigned)__cvta_generic_to_shared(sQ);
    const unsigned sKb = (unsigned)__cvta_generic_to_shared(sK);
    const unsigned sVb = (unsigned)__cvta_generic_to_shared(sV);
    const unsigned sOb = sHb;
    const unsigned sTb = sQb;

    const int tid = threadIdx.x;
    const int n = blockIdx.x;
    const int b = blockIdx.y;

    // ---------------- Phase 0: stage H = [X | STE] ----------------
    {
        const float4* X4 = reinterpret_cast<const float4*>(X);
        const float4* S4 = reinterpret_cast<const float4*>(STE);
        float4* sH4 = reinterpret_cast<float4*>(sH);
        const int base    = (b*T_*N_ + n) * (D_/4);
        const int tstride = N_ * (D_/4);
        #pragma unroll
        for (int idx = tid; idx < T_*16; idx += 384) {
            const int t = idx >> 4, j4 = idx & 15;
            const int g = base + t*tstride + j4;
            sH4[t*32 + j4]      = X4[g];
            sH4[t*32 + 16 + j4] = S4[g];
        }
    }
    __syncthreads();

    const int j  = tid & 63;
    const int g  = tid >> 6;      // 0..5
    const int t0 = g * 8;

    // ---------------- Phase 1: q,k,v = relu(H @ W + b), packed f32x2 over k ----------------
    {
        u64 aq[8], ak[8], av[8];
        const u64 bq = pack2(__ldg(b12 + j), 0.f);
        const u64 bk = pack2(__ldg(b13 + j), 0.f);
        const u64 bv = pack2(__ldg(b14 + j), 0.f);
        #pragma unroll
        for (int i = 0; i < 8; i++) { aq[i]=bq; ak[i]=bk; av[i]=bv; }

        const u64* wq = gWqkv + j;            // [kp][64]
        const u64* wk = gWqkv + 4096 + j;
        const u64* wv = gWqkv + 8192 + j;
        const unsigned hrow = sHb + t0 * 512; // 128 floats/row = 512 B

        #pragma unroll 4
        for (int kp = 0; kp < 64; kp += 2) {
            const u64 wq0 = __ldg(wq + kp*64), wq1 = __ldg(wq + (kp+1)*64);
            const u64 wk0 = __ldg(wk + kp*64), wk1 = __ldg(wk + (kp+1)*64);
            const u64 wv0 = __ldg(wv + kp*64), wv1 = __ldg(wv + (kp+1)*64);
            #pragma unroll
            for (int tt = 0; tt < 8; tt++) {
                u64 h01, h23;
                lds2x64(h01, h23, hrow + tt*512 + kp*8);
                fma2(aq[tt], h01, wq0); fma2(aq[tt], h23, wq1);
                fma2(ak[tt], h01, wk0); fma2(ak[tt], h23, wk1);
                fma2(av[tt], h01, wv0); fma2(av[tt], h23, wv1);
            }
        }
        #pragma unroll
        for (int tt = 0; tt < 8; tt++) {
            const float2 fq = unpack2(aq[tt]);
            const float2 fk = unpack2(ak[tt]);
            const float2 fv = unpack2(av[tt]);
            sQ[(t0+tt)*SP + j] = fmaxf(fq.x + fq.y, 0.f);
            sK[(t0+tt)*SP + j] = fmaxf(fk.x + fk.y, 0.f);
            sV[(t0+tt)*SP + j] = fmaxf(fv.x + fv.y, 0.f);
        }
    }
    __syncthreads();

    // ---------------- Phase 2: attention, one (head, q-row) per thread ----------------
    // q,k >= 0 post-ReLU => scores bounded above; single-pass exp-sum softmax.
    {
        const int h = tid / 48;          // 0..7
        const int r = tid - h * 48;      // 0..47
        const unsigned hoff = h * 32;    // 8 floats = 32 B per head

        u64 q01, q23, q45, q67;
        lds2x64(q01, q23, sQb + r*SPB + hoff);
        lds2x64(q45, q67, sQb + r*SPB + hoff + 16);

        u64 o01 = 0, o23 = 0, o45 = 0, o67 = 0;
        float l = 0.f;
        const float sc = 0.35355339059327373f;  // 1/sqrt(8)

        #pragma unroll 4
        for (int p = 0; p < T_; p++) {
            u64 k01, k23, k45, k67, v01, v23, v45, v67;
            lds2x64(k01, k23, sKb + p*SPB + hoff);
            lds2x64(k45, k67, sKb + p*SPB + hoff + 16);
            lds2x64(v01, v23, sVb + p*SPB + hoff);
            lds2x64(v45, v67, sVb + p*SPB + hoff + 16);
            u64 s2 = mul2(q01, k01);
            fma2(s2, q23, k23); fma2(s2, q45, k45); fma2(s2, q67, k67);
            const float2 f = unpack2(s2);
            const float e = __expf((f.x + f.y) * sc);
            l += e;
            const u64 e2 = pack2(e, e);
            fma2(o01, e2, v01); fma2(o23, e2, v23);
            fma2(o45, e2, v45); fma2(o67, e2, v67);
        }
        const float inv = 1.f / l;
        const u64 i2 = pack2(inv, inv);
        sts2x64(sOb + r*SPB + hoff,      mul2(o01, i2), mul2(o23, i2));
        sts2x64(sOb + r*SPB + hoff + 16, mul2(o45, i2), mul2(o67, i2));
    }
    __syncthreads();

    // ---------------- Phase 3a: mid = relu(attnOut @ W15 + b15) ----------------
    {
        u64 a[8];
        const u64 bb = pack2(__ldg(b15 + j), 0.f);
        #pragma unroll
        for (int i = 0; i < 8; i++) a[i] = bb;
        const u64* w = gW56 + j;
        const unsigned orow = sOb + t0 * SPB;
        #pragma unroll 4
        for (int kp = 0; kp < 32; kp += 2) {
            const u64 w0 = __ldg(w + kp*64), w1 = __ldg(w + (kp+1)*64);
            #pragma unroll
            for (int tt = 0; tt < 8; tt++) {
                u64 h01, h23;
                lds2x64(h01, h23, orow + tt*SPB + kp*8);
                fma2(a[tt], h01, w0); fma2(a[tt], h23, w1);
            }
        }
        __syncthreads();   // all reads of sO done before sT(=sQ) writes land
        #pragma unroll
        for (int tt = 0; tt < 8; tt++) {
            const float2 f = unpack2(a[tt]);
            sT[(t0+tt)*SP + j] = fmaxf(f.x + f.y, 0.f);
        }
    }
    __syncthreads();

    // ---------------- Phase 3b: out = mid @ W16 + b16 ----------------
    {
        u64 a[8];
        const u64 bb = pack2(__ldg(b16 + j), 0.f);
        #pragma unroll
        for (int i = 0; i < 8; i++) a[i] = bb;
        const u64* w = gW56 + 2048 + j;
        const unsigned trow = sTb + t0 * SPB;
        #pragma unroll 4
        for (int kp = 0; kp < 32; kp += 2) {
            const u64 w0 = __ldg(w + kp*64), w1 = __ldg(w + (kp+1)*64);
            #pragma unroll
            for (int tt = 0; tt < 8; tt++) {
                u64 h01, h23;
                lds2x64(h01, h23, trow + tt*SPB + kp*8);
                fma2(a[tt], h01, w0); fma2(a[tt], h23, w1);
            }
        }
        const int obase = (b*T_*N_ + n) * D_ + j;
        #pragma unroll
        for (int tt = 0; tt < 8; tt++) {
            const float2 f = unpack2(a[tt]);
            out[obase + (t0+tt)*N_*D_] = f.x + f.y;
        }
    }
}

extern "C" void kernel_launch(void* const* d_in, const int* in_sizes, int n_in,
                              void* d_out, int out_size)
{
    (void)in_sizes; (void)n_in; (void)out_size;
    cudaFuncSetAttribute(fused_temporal_attn,
                         cudaFuncAttributeMaxDynamicSharedMemorySize, SMEM_BYTES);
    pack_weights<<<64, 256>>>(
        (const float*)d_in[2], (const float*)d_in[4], (const float*)d_in[6],
        (const float*)d_in[8], (const float*)d_in[10]);
    dim3 grid(N_, B_);
    fused_temporal_attn<<<grid, 384, SMEM_BYTES>>>(
        (const float*)d_in[0],  (const float*)d_in[1],
        (const float*)d_in[3],  (const float*)d_in[5],
        (const float*)d_in[7],  (const float*)d_in[9],
        (const float*)d_in[11],
        (float*)d_out);
}